// round 2
// baseline (speedup 1.0000x reference)
#include <cuda_runtime.h>
#include <cstddef>

#define N_NODES 100000
#define N_EDGES 1600000
#define IN_F    48
#define EDGE_F  32
#define CAT_F   96      // 2*IN_F
#define HID_F   128
#define OUT_F   64

// ---------------- scratch (static device globals; no runtime alloc) ----------------
__device__ float g_deg [N_NODES];                   // in-degree (float)
__device__ float g_sum0[(size_t)N_NODES * IN_F];    // sum of nfeat[src]*e per dst
__device__ float g_h   [(size_t)N_NODES * CAT_F];   // concat(nfeat, h_neigh0)
__device__ float g_sum1[(size_t)N_NODES * CAT_F];   // sum of h[src] per dst
__device__ float g_h1  [(size_t)N_NODES * HID_F];   // layer-1 activations
__device__ float g_sum2[(size_t)N_NODES * HID_F];   // sum of h1[src] per dst

// ---------------- helpers ----------------
__device__ __forceinline__ void red_add_v4(float* p, float4 v) {
    asm volatile("red.global.add.v4.f32 [%0], {%1, %2, %3, %4};"
                 :: "l"(p), "f"(v.x), "f"(v.y), "f"(v.z), "f"(v.w) : "memory");
}
__device__ __forceinline__ void red_add_f32(float* p, float v) {
    asm volatile("red.global.add.f32 [%0], %1;" :: "l"(p), "f"(v) : "memory");
}

// ---------------- zero scratch accumulators ----------------
// total float4s: N*(1 + 48 + 96 + 128)/4 = 6,825,000
__global__ void k_zero() {
    size_t i = (size_t)blockIdx.x * blockDim.x + threadIdx.x;
    const float4 z = make_float4(0.f, 0.f, 0.f, 0.f);
    size_t n;
    n = N_NODES / 4;                    if (i < n) { ((float4*)g_deg )[i] = z; return; } i -= n;
    n = (size_t)N_NODES * IN_F  / 4;    if (i < n) { ((float4*)g_sum0)[i] = z; return; } i -= n;
    n = (size_t)N_NODES * CAT_F / 4;    if (i < n) { ((float4*)g_sum1)[i] = z; return; } i -= n;
    n = (size_t)N_NODES * HID_F / 4;    if (i < n) { ((float4*)g_sum2)[i] = z; return; }
}

// ---------------- edge pass 1: e = relu(efeat@We+be); scatter nfeat[src]*e; degree ----------------
__global__ void __launch_bounds__(256) k_edge1(const float* __restrict__ efeat,
                                               const float* __restrict__ nfeat,
                                               const int*   __restrict__ src,
                                               const int*   __restrict__ dst,
                                               const float* __restrict__ We,
                                               const float* __restrict__ be) {
    __shared__ __align__(16) float sWe[EDGE_F * IN_F];   // [k][j]
    __shared__ float sbe[IN_F];
    for (int i = threadIdx.x; i < EDGE_F * IN_F; i += blockDim.x) sWe[i] = We[i];
    for (int i = threadIdx.x; i < IN_F; i += blockDim.x) sbe[i] = be[i];
    __syncthreads();

    int e = blockIdx.x * blockDim.x + threadIdx.x;
    if (e >= N_EDGES) return;

    float ef[EDGE_F];
    const float4* ep = (const float4*)(efeat + (size_t)e * EDGE_F);
    #pragma unroll
    for (int i = 0; i < EDGE_F / 4; i++) {
        float4 v = ep[i];
        ef[4*i+0] = v.x; ef[4*i+1] = v.y; ef[4*i+2] = v.z; ef[4*i+3] = v.w;
    }

    int s = src[e], d = dst[e];
    const float4* np = (const float4*)(nfeat + (size_t)s * IN_F);
    float* op = g_sum0 + (size_t)d * IN_F;

    #pragma unroll 1
    for (int j = 0; j < IN_F / 4; j++) {
        float4 a;
        a.x = sbe[4*j+0]; a.y = sbe[4*j+1]; a.z = sbe[4*j+2]; a.w = sbe[4*j+3];
        #pragma unroll
        for (int k = 0; k < EDGE_F; k++) {
            float4 w = *(const float4*)&sWe[k * IN_F + 4*j];
            a.x = fmaf(ef[k], w.x, a.x);
            a.y = fmaf(ef[k], w.y, a.y);
            a.z = fmaf(ef[k], w.z, a.z);
            a.w = fmaf(ef[k], w.w, a.w);
        }
        a.x = fmaxf(a.x, 0.f); a.y = fmaxf(a.y, 0.f);
        a.z = fmaxf(a.z, 0.f); a.w = fmaxf(a.w, 0.f);
        float4 nf = np[j];
        a.x *= nf.x; a.y *= nf.y; a.z *= nf.z; a.w *= nf.w;
        red_add_v4(op + 4*j, a);
    }
    red_add_f32(g_deg + d, 1.0f);
}

// ---------------- build h = concat(nfeat, sum0/deg) ----------------
__global__ void __launch_bounds__(256) k_build_h(const float* __restrict__ nfeat) {
    int n = blockIdx.x * blockDim.x + threadIdx.x;
    if (n >= N_NODES) return;
    float invd = 1.0f / fmaxf(g_deg[n], 1.0f);
    float4*       hp = (float4*)(g_h + (size_t)n * CAT_F);
    const float4* np = (const float4*)(nfeat + (size_t)n * IN_F);
    const float4* sp = (const float4*)(g_sum0 + (size_t)n * IN_F);
    #pragma unroll
    for (int i = 0; i < IN_F / 4; i++) hp[i] = np[i];
    #pragma unroll
    for (int i = 0; i < IN_F / 4; i++) {
        float4 v = sp[i];
        v.x *= invd; v.y *= invd; v.z *= invd; v.w *= invd;
        hp[IN_F/4 + i] = v;
    }
}

// ---------------- scatter h -> sum1 ----------------
__global__ void __launch_bounds__(256) k_scatter_h(const int* __restrict__ src,
                                                   const int* __restrict__ dst) {
    int e = blockIdx.x * blockDim.x + threadIdx.x;
    if (e >= N_EDGES) return;
    int s = src[e], d = dst[e];
    const float4* vp = (const float4*)(g_h + (size_t)s * CAT_F);
    float* op = g_sum1 + (size_t)d * CAT_F;
    #pragma unroll
    for (int j = 0; j < CAT_F / 4; j++) red_add_v4(op + 4*j, vp[j]);
}

// ---------------- scatter h1 -> sum2 ----------------
__global__ void __launch_bounds__(256) k_scatter_h1(const int* __restrict__ src,
                                                    const int* __restrict__ dst) {
    int e = blockIdx.x * blockDim.x + threadIdx.x;
    if (e >= N_EDGES) return;
    int s = src[e], d = dst[e];
    const float4* vp = (const float4*)(g_h1 + (size_t)s * HID_F);
    float* op = g_sum2 + (size_t)d * HID_F;
    #pragma unroll
    for (int j = 0; j < HID_F / 4; j++) red_add_v4(op + 4*j, vp[j]);
}

// ---------------- SAGEConv1: h1 = relu(h@W1s + (sum1/deg)@W1n + b1) ----------------
// warp handles 8 nodes; lane computes 4 consecutive outputs (128 = 32*4)
// mean scaling folded in: neighbor-half x vectors are multiplied by 1/deg at load.
__global__ void __launch_bounds__(256) k_sage1(const float* __restrict__ W1s,
                                               const float* __restrict__ W1n,
                                               const float* __restrict__ b1) {
    int gwarp = (blockIdx.x * 256 + threadIdx.x) >> 5;
    int lane  = threadIdx.x & 31;
    int n0 = gwarp * 8;
    if (n0 >= N_NODES) return;
    int c = lane * 4;

    float invd[8];
    #pragma unroll
    for (int j = 0; j < 8; j++) invd[j] = 1.0f / fmaxf(g_deg[n0 + j], 1.0f);

    float acc[8][4];
    #pragma unroll
    for (int j = 0; j < 8; j++) { acc[j][0]=0.f; acc[j][1]=0.f; acc[j][2]=0.f; acc[j][3]=0.f; }

    #pragma unroll 1
    for (int half = 0; half < 2; half++) {
        const float* xb = (half == 0 ? g_h : g_sum1) + (size_t)n0 * CAT_F;
        const float* W  = (half == 0 ? W1s : W1n);
        #pragma unroll 1
        for (int k0 = 0; k0 < CAT_F; k0 += 4) {
            float4 xv[8];
            #pragma unroll
            for (int j = 0; j < 8; j++) {
                xv[j] = *(const float4*)(xb + (size_t)j * CAT_F + k0);
                if (half == 1) {
                    xv[j].x *= invd[j]; xv[j].y *= invd[j];
                    xv[j].z *= invd[j]; xv[j].w *= invd[j];
                }
            }
            #pragma unroll
            for (int kk = 0; kk < 4; kk++) {
                float4 w = *(const float4*)(W + (size_t)(k0 + kk) * HID_F + c);
                #pragma unroll
                for (int j = 0; j < 8; j++) {
                    float x = (kk == 0) ? xv[j].x : (kk == 1) ? xv[j].y : (kk == 2) ? xv[j].z : xv[j].w;
                    acc[j][0] = fmaf(x, w.x, acc[j][0]);
                    acc[j][1] = fmaf(x, w.y, acc[j][1]);
                    acc[j][2] = fmaf(x, w.z, acc[j][2]);
                    acc[j][3] = fmaf(x, w.w, acc[j][3]);
                }
            }
        }
    }

    float4 b = *(const float4*)(b1 + c);
    #pragma unroll
    for (int j = 0; j < 8; j++) {
        float4 r;
        r.x = fmaxf(acc[j][0] + b.x, 0.f);
        r.y = fmaxf(acc[j][1] + b.y, 0.f);
        r.z = fmaxf(acc[j][2] + b.z, 0.f);
        r.w = fmaxf(acc[j][3] + b.w, 0.f);
        *(float4*)(g_h1 + (size_t)(n0 + j) * HID_F + c) = r;
    }
}

// ---------------- SAGEConv2: out = h1@W2s + (sum2/deg)@W2n + b2 ----------------
// warp handles 8 nodes; lane computes 2 consecutive outputs (64 = 32*2)
__global__ void __launch_bounds__(256) k_sage2(const float* __restrict__ W2s,
                                               const float* __restrict__ W2n,
                                               const float* __restrict__ b2,
                                               float* __restrict__ out) {
    int gwarp = (blockIdx.x * 256 + threadIdx.x) >> 5;
    int lane  = threadIdx.x & 31;
    int n0 = gwarp * 8;
    if (n0 >= N_NODES) return;
    int c = lane * 2;

    float invd[8];
    #pragma unroll
    for (int j = 0; j < 8; j++) invd[j] = 1.0f / fmaxf(g_deg[n0 + j], 1.0f);

    float acc[8][2];
    #pragma unroll
    for (int j = 0; j < 8; j++) { acc[j][0]=0.f; acc[j][1]=0.f; }

    #pragma unroll 1
    for (int half = 0; half < 2; half++) {
        const float* xb = (half == 0 ? g_h1 : g_sum2) + (size_t)n0 * HID_F;
        const float* W  = (half == 0 ? W2s : W2n);
        #pragma unroll 1
        for (int k0 = 0; k0 < HID_F; k0 += 4) {
            float4 xv[8];
            #pragma unroll
            for (int j = 0; j < 8; j++) {
                xv[j] = *(const float4*)(xb + (size_t)j * HID_F + k0);
                if (half == 1) {
                    xv[j].x *= invd[j]; xv[j].y *= invd[j];
                    xv[j].z *= invd[j]; xv[j].w *= invd[j];
                }
            }
            #pragma unroll
            for (int kk = 0; kk < 4; kk++) {
                float2 w = *(const float2*)(W + (size_t)(k0 + kk) * OUT_F + c);
                #pragma unroll
                for (int j = 0; j < 8; j++) {
                    float x = (kk == 0) ? xv[j].x : (kk == 1) ? xv[j].y : (kk == 2) ? xv[j].z : xv[j].w;
                    acc[j][0] = fmaf(x, w.x, acc[j][0]);
                    acc[j][1] = fmaf(x, w.y, acc[j][1]);
                }
            }
        }
    }

    float2 b = *(const float2*)(b2 + c);
    #pragma unroll
    for (int j = 0; j < 8; j++) {
        float2 r;
        r.x = acc[j][0] + b.x;
        r.y = acc[j][1] + b.y;
        *(float2*)(out + (size_t)(n0 + j) * OUT_F + c) = r;
    }
}

// ---------------- launch ----------------
extern "C" void kernel_launch(void* const* d_in, const int* in_sizes, int n_in,
                              void* d_out, int out_size) {
    const float* nfeat = (const float*)d_in[0];
    const float* efeat = (const float*)d_in[1];
    const int*   src   = (const int*)  d_in[2];
    const int*   dst   = (const int*)  d_in[3];
    const float* We    = (const float*)d_in[4];
    const float* be    = (const float*)d_in[5];
    const float* W1s   = (const float*)d_in[6];
    const float* W1n   = (const float*)d_in[7];
    const float* b1    = (const float*)d_in[8];
    const float* W2s   = (const float*)d_in[9];
    const float* W2n   = (const float*)d_in[10];
    const float* b2    = (const float*)d_in[11];
    float* out = (float*)d_out;

    const int TPB = 256;
    const size_t zero4 = (size_t)N_NODES * (1 + IN_F + CAT_F + HID_F) / 4;   // 6,825,000
    const int zero_blocks = (int)((zero4 + TPB - 1) / TPB);
    const int edge_blocks = (N_EDGES + TPB - 1) / TPB;
    const int node_blocks = (N_NODES + TPB - 1) / TPB;
    const int sage_blocks = ((N_NODES / 8) * 32 + TPB - 1) / TPB;  // 12500 warps

    k_zero      <<<zero_blocks, TPB>>>();
    k_edge1     <<<edge_blocks, TPB>>>(efeat, nfeat, src, dst, We, be);
    k_build_h   <<<node_blocks, TPB>>>(nfeat);
    k_scatter_h <<<edge_blocks, TPB>>>(src, dst);
    k_sage1     <<<sage_blocks, TPB>>>(W1s, W1n, b1);
    k_scatter_h1<<<edge_blocks, TPB>>>(src, dst);
    k_sage2     <<<sage_blocks, TPB>>>(W2s, W2n, b2, out);
}

// round 3
// speedup vs baseline: 1.3360x; 1.3360x over previous
#include <cuda_runtime.h>
#include <cstddef>

#define N_NODES 100000
#define N_EDGES 1600000
#define IN_F    48
#define EDGE_F  32
#define CAT_F   96
#define HID_F   128
#define OUT_F   64

#define SCAN_T  1024
#define CHUNK   ((N_NODES + SCAN_T - 1) / SCAN_T)

__device__ int   g_deg_i [N_NODES];
__device__ int   g_rowptr[N_NODES + 1];
__device__ int   g_cursor[N_NODES];
__device__ int   g_csr_eid[N_EDGES];
__device__ int   g_csr_src[N_EDGES];
__device__ float g_msg [(size_t)N_EDGES * IN_F];
__device__ float g_h   [(size_t)N_NODES * CAT_F];
__device__ float g_hn1 [(size_t)N_NODES * CAT_F];
__device__ float g_h1  [(size_t)N_NODES * HID_F];
__device__ float g_hn2 [(size_t)N_NODES * HID_F];

__global__ void k_zero_hist() {
    int i = blockIdx.x * blockDim.x + threadIdx.x;
    if (i < N_NODES) g_deg_i[i] = 0;
}

__global__ void __launch_bounds__(256) k_hist(const int* __restrict__ dst) {
    int e = blockIdx.x * blockDim.x + threadIdx.x;
    if (e < N_EDGES) atomicAdd(&g_deg_i[dst[e]], 1);
}

__global__ void __launch_bounds__(SCAN_T) k_scan() {
    __shared__ int sh[SCAN_T];
    int t = threadIdx.x;
    int start = t * CHUNK;
    int end = start + CHUNK; if (end > N_NODES) end = N_NODES;
    int s = 0;
    if (start < N_NODES) for (int i = start; i < end; i++) s += g_deg_i[i];
    sh[t] = s;
    __syncthreads();
    for (int d = 1; d < SCAN_T; d <<= 1) {
        int v = (t >= d) ? sh[t - d] : 0;
        __syncthreads();
        sh[t] += v;
        __syncthreads();
    }
    int off = sh[t] - s;
    if (start < N_NODES) {
        for (int i = start; i < end; i++) {
            g_rowptr[i] = off;
            g_cursor[i] = off;
            off += g_deg_i[i];
        }
        if (end == N_NODES) g_rowptr[N_NODES] = off;
    }
}

__global__ void __launch_bounds__(256) k_place(const int* __restrict__ src,
                                               const int* __restrict__ dst) {
    int e = blockIdx.x * blockDim.x + threadIdx.x;
    if (e >= N_EDGES) return;
    int p = atomicAdd(&g_cursor[dst[e]], 1);
    g_csr_eid[p] = e;
    g_csr_src[p] = src[e];
}

__global__ void __launch_bounds__(256) k_edge_mlp(const float* __restrict__ efeat,
                                                  const float* __restrict__ nfeat,
                                                  const float* __restrict__ We,
                                                  const float* __restrict__ be) {
    __shared__ __align__(16) float sWe[EDGE_F * IN_F];
    __shared__ float sbe[IN_F];
    for (int i = threadIdx.x; i < EDGE_F * IN_F; i += blockDim.x) sWe[i] = We[i];
    for (int i = threadIdx.x; i < IN_F; i += blockDim.x) sbe[i] = be[i];
    __syncthreads();

    int p = blockIdx.x * blockDim.x + threadIdx.x;
    if (p >= N_EDGES) return;
    int eid = g_csr_eid[p];
    int s   = g_csr_src[p];

    float ef[EDGE_F];
    const float4* ep = (const float4*)(efeat + (size_t)eid * EDGE_F);
    #pragma unroll
    for (int i = 0; i < EDGE_F / 4; i++) {
        float4 v = ep[i];
        ef[4*i+0] = v.x; ef[4*i+1] = v.y; ef[4*i+2] = v.z; ef[4*i+3] = v.w;
    }

    const float4* np = (const float4*)(nfeat + (size_t)s * IN_F);
    float4*       op = (float4*)(g_msg + (size_t)p * IN_F);

    #pragma unroll 1
    for (int j = 0; j < IN_F / 4; j++) {
        float4 a;
        a.x = sbe[4*j+0]; a.y = sbe[4*j+1]; a.z = sbe[4*j+2]; a.w = sbe[4*j+3];
        #pragma unroll
        for (int k = 0; k < EDGE_F; k++) {
            float4 w = *(const float4*)&sWe[k * IN_F + 4*j];
            a.x = fmaf(ef[k], w.x, a.x);
            a.y = fmaf(ef[k], w.y, a.y);
            a.z = fmaf(ef[k], w.z, a.z);
            a.w = fmaf(ef[k], w.w, a.w);
        }
        a.x = fmaxf(a.x, 0.f); a.y = fmaxf(a.y, 0.f);
        a.z = fmaxf(a.z, 0.f); a.w = fmaxf(a.w, 0.f);
        float4 nf = np[j];
        a.x *= nf.x; a.y *= nf.y; a.z *= nf.z; a.w *= nf.w;
        op[j] = a;
    }
}

// half-warp per node: streams g_msg, writes h = [nfeat | mean(msg)]
__global__ void __launch_bounds__(256) k_gather0(const float* __restrict__ nfeat) {
    int gw   = (blockIdx.x * 256 + threadIdx.x) >> 5;
    int lane = threadIdx.x & 31;
    int half = lane >> 4, sub = lane & 15;
    int node = gw * 2 + half;
    if (node >= N_NODES) return;
    bool active = sub < (IN_F / 4);

    int lo = g_rowptr[node], hi = g_rowptr[node + 1];
    float4 acc = make_float4(0.f, 0.f, 0.f, 0.f);
    if (active) {
        for (int p = lo; p < hi; p++) {
            float4 v = *(const float4*)(g_msg + (size_t)p * IN_F + sub * 4);
            acc.x += v.x; acc.y += v.y; acc.z += v.z; acc.w += v.w;
        }
    }
    float invd = 1.0f / fmaxf((float)(hi - lo), 1.0f);
    if (active) {
        float4 nf = *(const float4*)(nfeat + (size_t)node * IN_F + sub * 4);
        *(float4*)(g_h + (size_t)node * CAT_F + sub * 4) = nf;
        acc.x *= invd; acc.y *= invd; acc.z *= invd; acc.w *= invd;
        *(float4*)(g_h + (size_t)node * CAT_F + IN_F + sub * 4) = acc;
    }
}

// warp per node: mean-gather of node vectors, binds globals inside device code
template <int F, bool FROM_H>
__global__ void __launch_bounds__(256) k_gather_nodes() {
    int node = (blockIdx.x * 256 + threadIdx.x) >> 5;
    int lane = threadIdx.x & 31;
    if (node >= N_NODES) return;
    const float* vals = FROM_H ? g_h  : g_h1;
    float*       outm = FROM_H ? g_hn1 : g_hn2;
    bool active = lane < (F / 4);

    int lo = g_rowptr[node], hi = g_rowptr[node + 1];
    float4 acc = make_float4(0.f, 0.f, 0.f, 0.f);
    for (int p = lo; p < hi; p++) {
        int s = g_csr_src[p];
        if (active) {
            float4 v = *(const float4*)(vals + (size_t)s * F + lane * 4);
            acc.x += v.x; acc.y += v.y; acc.z += v.z; acc.w += v.w;
        }
    }
    if (active) {
        float invd = 1.0f / fmaxf((float)(hi - lo), 1.0f);
        acc.x *= invd; acc.y *= invd; acc.z *= invd; acc.w *= invd;
        *(float4*)(outm + (size_t)node * F + lane * 4) = acc;
    }
}

__global__ void __launch_bounds__(256) k_sage1(const float* __restrict__ W1s,
                                               const float* __restrict__ W1n,
                                               const float* __restrict__ b1) {
    int gwarp = (blockIdx.x * 256 + threadIdx.x) >> 5;
    int lane  = threadIdx.x & 31;
    int n0 = gwarp * 8;
    if (n0 >= N_NODES) return;
    int c = lane * 4;

    float acc[8][4];
    #pragma unroll
    for (int j = 0; j < 8; j++) { acc[j][0]=0.f; acc[j][1]=0.f; acc[j][2]=0.f; acc[j][3]=0.f; }

    #pragma unroll 1
    for (int hf = 0; hf < 2; hf++) {
        const float* xb = (hf == 0 ? g_h : g_hn1) + (size_t)n0 * CAT_F;
        const float* W  = (hf == 0 ? W1s : W1n);
        #pragma unroll 1
        for (int k0 = 0; k0 < CAT_F; k0 += 4) {
            float4 xv[8];
            #pragma unroll
            for (int j = 0; j < 8; j++) xv[j] = *(const float4*)(xb + (size_t)j * CAT_F + k0);
            #pragma unroll
            for (int kk = 0; kk < 4; kk++) {
                float4 w = *(const float4*)(W + (size_t)(k0 + kk) * HID_F + c);
                #pragma unroll
                for (int j = 0; j < 8; j++) {
                    float x = (kk == 0) ? xv[j].x : (kk == 1) ? xv[j].y : (kk == 2) ? xv[j].z : xv[j].w;
                    acc[j][0] = fmaf(x, w.x, acc[j][0]);
                    acc[j][1] = fmaf(x, w.y, acc[j][1]);
                    acc[j][2] = fmaf(x, w.z, acc[j][2]);
                    acc[j][3] = fmaf(x, w.w, acc[j][3]);
                }
            }
        }
    }

    float4 b = *(const float4*)(b1 + c);
    #pragma unroll
    for (int j = 0; j < 8; j++) {
        float4 r;
        r.x = fmaxf(acc[j][0] + b.x, 0.f);
        r.y = fmaxf(acc[j][1] + b.y, 0.f);
        r.z = fmaxf(acc[j][2] + b.z, 0.f);
        r.w = fmaxf(acc[j][3] + b.w, 0.f);
        *(float4*)(g_h1 + (size_t)(n0 + j) * HID_F + c) = r;
    }
}

__global__ void __launch_bounds__(256) k_sage2(const float* __restrict__ W2s,
                                               const float* __restrict__ W2n,
                                               const float* __restrict__ b2,
                                               float* __restrict__ out) {
    int gwarp = (blockIdx.x * 256 + threadIdx.x) >> 5;
    int lane  = threadIdx.x & 31;
    int n0 = gwarp * 8;
    if (n0 >= N_NODES) return;
    int c = lane * 2;

    float acc[8][2];
    #pragma unroll
    for (int j = 0; j < 8; j++) { acc[j][0]=0.f; acc[j][1]=0.f; }

    #pragma unroll 1
    for (int hf = 0; hf < 2; hf++) {
        const float* xb = (hf == 0 ? g_h1 : g_hn2) + (size_t)n0 * HID_F;
        const float* W  = (hf == 0 ? W2s : W2n);
        #pragma unroll 1
        for (int k0 = 0; k0 < HID_F; k0 += 4) {
            float4 xv[8];
            #pragma unroll
            for (int j = 0; j < 8; j++) xv[j] = *(const float4*)(xb + (size_t)j * HID_F + k0);
            #pragma unroll
            for (int kk = 0; kk < 4; kk++) {
                float2 w = *(const float2*)(W + (size_t)(k0 + kk) * OUT_F + c);
                #pragma unroll
                for (int j = 0; j < 8; j++) {
                    float x = (kk == 0) ? xv[j].x : (kk == 1) ? xv[j].y : (kk == 2) ? xv[j].z : xv[j].w;
                    acc[j][0] = fmaf(x, w.x, acc[j][0]);
                    acc[j][1] = fmaf(x, w.y, acc[j][1]);
                }
            }
        }
    }

    float2 b = *(const float2*)(b2 + c);
    #pragma unroll
    for (int j = 0; j < 8; j++) {
        float2 r;
        r.x = acc[j][0] + b.x;
        r.y = acc[j][1] + b.y;
        *(float2*)(out + (size_t)(n0 + j) * OUT_F + c) = r;
    }
}

extern "C" void kernel_launch(void* const* d_in, const int* in_sizes, int n_in,
                              void* d_out, int out_size) {
    const float* nfeat = (const float*)d_in[0];
    const float* efeat = (const float*)d_in[1];
    const int*   src   = (const int*)  d_in[2];
    const int*   dst   = (const int*)  d_in[3];
    const float* We    = (const float*)d_in[4];
    const float* be    = (const float*)d_in[5];
    const float* W1s   = (const float*)d_in[6];
    const float* W1n   = (const float*)d_in[7];
    const float* b1    = (const float*)d_in[8];
    const float* W2s   = (const float*)d_in[9];
    const float* W2n   = (const float*)d_in[10];
    const float* b2    = (const float*)d_in[11];
    float* out = (float*)d_out;

    const int TPB = 256;
    const int edge_blocks = (N_EDGES + TPB - 1) / TPB;
    const int node_blocks = (N_NODES + TPB - 1) / TPB;
    const int g0_blocks   = (N_NODES + 15) / 16;   // 16 nodes per 256-thread block
    const int gw_blocks   = (N_NODES + 7) / 8;     // 8 nodes (warps) per block
    const int sage_blocks = (((N_NODES + 7) / 8) * 32 + TPB - 1) / TPB;

    k_zero_hist<<<node_blocks, TPB>>>();
    k_hist     <<<edge_blocks, TPB>>>(dst);
    k_scan     <<<1, SCAN_T>>>();
    k_place    <<<edge_blocks, TPB>>>(src, dst);
    k_edge_mlp <<<edge_blocks, TPB>>>(efeat, nfeat, We, be);
    k_gather0  <<<g0_blocks, TPB>>>(nfeat);
    k_gather_nodes<CAT_F, true ><<<gw_blocks, TPB>>>();
    k_sage1    <<<sage_blocks, TPB>>>(W1s, W1n, b1);
    k_gather_nodes<HID_F, false><<<gw_blocks, TPB>>>();
    k_sage2    <<<sage_blocks, TPB>>>(W2s, W2n, b2, out);
}

// round 5
// speedup vs baseline: 1.4093x; 1.0549x over previous
#include <cuda_runtime.h>
#include <cstddef>

#define N_NODES 100000
#define N_EDGES 1600000
#define IN_F    48
#define EDGE_F  32
#define CAT_F   96
#define HID_F   128
#define OUT_F   64

#define SCAN_T  1024
#define CHUNK   ((N_NODES + SCAN_T - 1) / SCAN_T)

__device__ int   g_deg_i [N_NODES];
__device__ int   g_rowptr[N_NODES + 1];
__device__ int   g_cursor[N_NODES];
__device__ int   g_csr_eid[N_EDGES];
__device__ int   g_csr_src[N_EDGES];
__device__ float g_msg [(size_t)N_EDGES * IN_F];
__device__ float g_h   [(size_t)N_NODES * CAT_F];
__device__ float g_hn1 [(size_t)N_NODES * CAT_F];
__device__ float g_h1  [(size_t)N_NODES * HID_F];
__device__ float g_z2  [(size_t)N_NODES * OUT_F];   // h1 @ W2n (pre-aggregation)

// ---------------- CSR build ----------------
__global__ void k_zero_hist() {
    int i = blockIdx.x * blockDim.x + threadIdx.x;
    if (i < N_NODES) g_deg_i[i] = 0;
}

__global__ void __launch_bounds__(256) k_hist(const int* __restrict__ dst) {
    int e = blockIdx.x * blockDim.x + threadIdx.x;
    if (e < N_EDGES) atomicAdd(&g_deg_i[dst[e]], 1);
}

__global__ void __launch_bounds__(SCAN_T) k_scan() {
    __shared__ int sh[SCAN_T];
    int t = threadIdx.x;
    int start = t * CHUNK;
    int end = start + CHUNK; if (end > N_NODES) end = N_NODES;
    int s = 0;
    if (start < N_NODES) for (int i = start; i < end; i++) s += g_deg_i[i];
    sh[t] = s;
    __syncthreads();
    for (int d = 1; d < SCAN_T; d <<= 1) {
        int v = (t >= d) ? sh[t - d] : 0;
        __syncthreads();
        sh[t] += v;
        __syncthreads();
    }
    int off = sh[t] - s;
    if (start < N_NODES) {
        for (int i = start; i < end; i++) {
            g_rowptr[i] = off;
            g_cursor[i] = off;
            off += g_deg_i[i];
        }
        if (end == N_NODES) g_rowptr[N_NODES] = off;
    }
}

__global__ void __launch_bounds__(256) k_place(const int* __restrict__ src,
                                               const int* __restrict__ dst) {
    int e = blockIdx.x * blockDim.x + threadIdx.x;
    if (e >= N_EDGES) return;
    int p = atomicAdd(&g_cursor[dst[e]], 1);
    g_csr_eid[p] = e;
    g_csr_src[p] = src[e];
}

// ---------------- edge MLP in CSR order ----------------
__global__ void __launch_bounds__(256) k_edge_mlp(const float* __restrict__ efeat,
                                                  const float* __restrict__ nfeat,
                                                  const float* __restrict__ We,
                                                  const float* __restrict__ be) {
    __shared__ __align__(16) float sWe[EDGE_F * IN_F];
    __shared__ float sbe[IN_F];
    for (int i = threadIdx.x; i < EDGE_F * IN_F; i += blockDim.x) sWe[i] = We[i];
    for (int i = threadIdx.x; i < IN_F; i += blockDim.x) sbe[i] = be[i];
    __syncthreads();

    int p = blockIdx.x * blockDim.x + threadIdx.x;
    if (p >= N_EDGES) return;
    int eid = g_csr_eid[p];
    int s   = g_csr_src[p];

    float ef[EDGE_F];
    const float4* ep = (const float4*)(efeat + (size_t)eid * EDGE_F);
    #pragma unroll
    for (int i = 0; i < EDGE_F / 4; i++) {
        float4 v = ep[i];
        ef[4*i+0] = v.x; ef[4*i+1] = v.y; ef[4*i+2] = v.z; ef[4*i+3] = v.w;
    }

    const float4* np = (const float4*)(nfeat + (size_t)s * IN_F);
    float4*       op = (float4*)(g_msg + (size_t)p * IN_F);

    #pragma unroll 1
    for (int j = 0; j < IN_F / 4; j++) {
        float4 a;
        a.x = sbe[4*j+0]; a.y = sbe[4*j+1]; a.z = sbe[4*j+2]; a.w = sbe[4*j+3];
        #pragma unroll
        for (int k = 0; k < EDGE_F; k++) {
            float4 w = *(const float4*)&sWe[k * IN_F + 4*j];
            a.x = fmaf(ef[k], w.x, a.x);
            a.y = fmaf(ef[k], w.y, a.y);
            a.z = fmaf(ef[k], w.z, a.z);
            a.w = fmaf(ef[k], w.w, a.w);
        }
        a.x = fmaxf(a.x, 0.f); a.y = fmaxf(a.y, 0.f);
        a.z = fmaxf(a.z, 0.f); a.w = fmaxf(a.w, 0.f);
        float4 nf = np[j];
        a.x *= nf.x; a.y *= nf.y; a.z *= nf.z; a.w *= nf.w;
        op[j] = a;
    }
}

// ---------------- gather0: h = [nfeat | mean(msg)], half-warp per node ----------------
__global__ void __launch_bounds__(256) k_gather0(const float* __restrict__ nfeat) {
    int gw   = (blockIdx.x * 256 + threadIdx.x) >> 5;
    int lane = threadIdx.x & 31;
    int half = lane >> 4, sub = lane & 15;
    int node = gw * 2 + half;
    if (node >= N_NODES) return;
    bool active = sub < (IN_F / 4);

    int lo = g_rowptr[node], hi = g_rowptr[node + 1];
    float4 a0 = make_float4(0.f,0.f,0.f,0.f), a1 = make_float4(0.f,0.f,0.f,0.f);
    if (active) {
        int p = lo;
        for (; p + 1 < hi; p += 2) {
            float4 v0 = *(const float4*)(g_msg + (size_t)p       * IN_F + sub * 4);
            float4 v1 = *(const float4*)(g_msg + (size_t)(p + 1) * IN_F + sub * 4);
            a0.x += v0.x; a0.y += v0.y; a0.z += v0.z; a0.w += v0.w;
            a1.x += v1.x; a1.y += v1.y; a1.z += v1.z; a1.w += v1.w;
        }
        if (p < hi) {
            float4 v = *(const float4*)(g_msg + (size_t)p * IN_F + sub * 4);
            a0.x += v.x; a0.y += v.y; a0.z += v.z; a0.w += v.w;
        }
    }
    if (active) {
        float invd = 1.0f / fmaxf((float)(hi - lo), 1.0f);
        float4 nf = *(const float4*)(nfeat + (size_t)node * IN_F + sub * 4);
        *(float4*)(g_h + (size_t)node * CAT_F + sub * 4) = nf;
        float4 acc;
        acc.x = (a0.x + a1.x) * invd; acc.y = (a0.y + a1.y) * invd;
        acc.z = (a0.z + a1.z) * invd; acc.w = (a0.w + a1.w) * invd;
        *(float4*)(g_h + (size_t)node * CAT_F + IN_F + sub * 4) = acc;
    }
}

// ---------------- gather1: hn1 = mean(h[src]) per node, warp per node, unroll 2 ----------------
__global__ void __launch_bounds__(256) k_gather_h() {
    int node = (blockIdx.x * 256 + threadIdx.x) >> 5;
    int lane = threadIdx.x & 31;
    if (node >= N_NODES) return;
    bool active = lane < (CAT_F / 4);

    int lo = g_rowptr[node], hi = g_rowptr[node + 1];
    float4 a0 = make_float4(0.f,0.f,0.f,0.f), a1 = make_float4(0.f,0.f,0.f,0.f);
    int p = lo;
    for (; p + 1 < hi; p += 2) {
        int s0 = g_csr_src[p], s1 = g_csr_src[p + 1];
        if (active) {
            float4 v0 = *(const float4*)(g_h + (size_t)s0 * CAT_F + lane * 4);
            float4 v1 = *(const float4*)(g_h + (size_t)s1 * CAT_F + lane * 4);
            a0.x += v0.x; a0.y += v0.y; a0.z += v0.z; a0.w += v0.w;
            a1.x += v1.x; a1.y += v1.y; a1.z += v1.z; a1.w += v1.w;
        }
    }
    if (p < hi) {
        int s = g_csr_src[p];
        if (active) {
            float4 v = *(const float4*)(g_h + (size_t)s * CAT_F + lane * 4);
            a0.x += v.x; a0.y += v.y; a0.z += v.z; a0.w += v.w;
        }
    }
    if (active) {
        float invd = 1.0f / fmaxf((float)(hi - lo), 1.0f);
        float4 acc;
        acc.x = (a0.x + a1.x) * invd; acc.y = (a0.y + a1.y) * invd;
        acc.z = (a0.z + a1.z) * invd; acc.w = (a0.w + a1.w) * invd;
        *(float4*)(g_hn1 + (size_t)node * CAT_F + lane * 4) = acc;
    }
}

// ---------------- SAGEConv1: h1 = relu(h@W1s + hn1@W1n + b1) ----------------
__global__ void __launch_bounds__(256) k_sage1(const float* __restrict__ W1s,
                                               const float* __restrict__ W1n,
                                               const float* __restrict__ b1) {
    int gwarp = (blockIdx.x * 256 + threadIdx.x) >> 5;
    int lane  = threadIdx.x & 31;
    int n0 = gwarp * 8;
    if (n0 >= N_NODES) return;
    int c = lane * 4;

    float acc[8][4];
    #pragma unroll
    for (int j = 0; j < 8; j++) { acc[j][0]=0.f; acc[j][1]=0.f; acc[j][2]=0.f; acc[j][3]=0.f; }

    #pragma unroll 1
    for (int hf = 0; hf < 2; hf++) {
        const float* xb = (hf == 0 ? g_h : g_hn1) + (size_t)n0 * CAT_F;
        const float* W  = (hf == 0 ? W1s : W1n);
        #pragma unroll 1
        for (int k0 = 0; k0 < CAT_F; k0 += 4) {
            float4 xv[8];
            #pragma unroll
            for (int j = 0; j < 8; j++) xv[j] = *(const float4*)(xb + (size_t)j * CAT_F + k0);
            #pragma unroll
            for (int kk = 0; kk < 4; kk++) {
                float4 w = *(const float4*)(W + (size_t)(k0 + kk) * HID_F + c);
                #pragma unroll
                for (int j = 0; j < 8; j++) {
                    float x = (kk == 0) ? xv[j].x : (kk == 1) ? xv[j].y : (kk == 2) ? xv[j].z : xv[j].w;
                    acc[j][0] = fmaf(x, w.x, acc[j][0]);
                    acc[j][1] = fmaf(x, w.y, acc[j][1]);
                    acc[j][2] = fmaf(x, w.z, acc[j][2]);
                    acc[j][3] = fmaf(x, w.w, acc[j][3]);
                }
            }
        }
    }

    float4 b = *(const float4*)(b1 + c);
    #pragma unroll
    for (int j = 0; j < 8; j++) {
        float4 r;
        r.x = fmaxf(acc[j][0] + b.x, 0.f);
        r.y = fmaxf(acc[j][1] + b.y, 0.f);
        r.z = fmaxf(acc[j][2] + b.z, 0.f);
        r.w = fmaxf(acc[j][3] + b.w, 0.f);
        *(float4*)(g_h1 + (size_t)(n0 + j) * HID_F + c) = r;
    }
}

// ---------------- premul2: z2 = h1 @ W2n ----------------
__global__ void __launch_bounds__(256) k_premul2(const float* __restrict__ W2n) {
    int gwarp = (blockIdx.x * 256 + threadIdx.x) >> 5;
    int lane  = threadIdx.x & 31;
    int n0 = gwarp * 8;
    if (n0 >= N_NODES) return;
    int c = lane * 2;

    float acc[8][2];
    #pragma unroll
    for (int j = 0; j < 8; j++) { acc[j][0]=0.f; acc[j][1]=0.f; }

    const float* xb = g_h1 + (size_t)n0 * HID_F;
    #pragma unroll 1
    for (int k0 = 0; k0 < HID_F; k0 += 4) {
        float4 xv[8];
        #pragma unroll
        for (int j = 0; j < 8; j++) xv[j] = *(const float4*)(xb + (size_t)j * HID_F + k0);
        #pragma unroll
        for (int kk = 0; kk < 4; kk++) {
            float2 w = *(const float2*)(W2n + (size_t)(k0 + kk) * OUT_F + c);
            #pragma unroll
            for (int j = 0; j < 8; j++) {
                float x = (kk == 0) ? xv[j].x : (kk == 1) ? xv[j].y : (kk == 2) ? xv[j].z : xv[j].w;
                acc[j][0] = fmaf(x, w.x, acc[j][0]);
                acc[j][1] = fmaf(x, w.y, acc[j][1]);
            }
        }
    }

    #pragma unroll
    for (int j = 0; j < 8; j++) {
        float2 r; r.x = acc[j][0]; r.y = acc[j][1];
        *(float2*)(g_z2 + (size_t)(n0 + j) * OUT_F + c) = r;
    }
}

// ---------------- sage2 fused: out = h1@W2s + mean(z2[src]) + b2 ----------------
__global__ void __launch_bounds__(256) k_sage2f(const float* __restrict__ W2s,
                                                const float* __restrict__ b2,
                                                float* __restrict__ out) {
    int gwarp = (blockIdx.x * 256 + threadIdx.x) >> 5;
    int lane  = threadIdx.x & 31;
    int n0 = gwarp * 8;
    if (n0 >= N_NODES) return;
    int c = lane * 2;

    float acc[8][2];
    #pragma unroll
    for (int j = 0; j < 8; j++) { acc[j][0]=0.f; acc[j][1]=0.f; }

    // GEMM: h1 @ W2s
    const float* xb = g_h1 + (size_t)n0 * HID_F;
    #pragma unroll 1
    for (int k0 = 0; k0 < HID_F; k0 += 4) {
        float4 xv[8];
        #pragma unroll
        for (int j = 0; j < 8; j++) xv[j] = *(const float4*)(xb + (size_t)j * HID_F + k0);
        #pragma unroll
        for (int kk = 0; kk < 4; kk++) {
            float2 w = *(const float2*)(W2s + (size_t)(k0 + kk) * OUT_F + c);
            #pragma unroll
            for (int j = 0; j < 8; j++) {
                float x = (kk == 0) ? xv[j].x : (kk == 1) ? xv[j].y : (kk == 2) ? xv[j].z : xv[j].w;
                acc[j][0] = fmaf(x, w.x, acc[j][0]);
                acc[j][1] = fmaf(x, w.y, acc[j][1]);
            }
        }
    }

    // fused gather: acc[j] += mean over edges of z2[src][c..c+1]
    #pragma unroll 1
    for (int j = 0; j < 8; j++) {
        int node = n0 + j;
        int lo = g_rowptr[node], hi = g_rowptr[node + 1];
        float2 a0 = make_float2(0.f, 0.f), a1 = make_float2(0.f, 0.f);
        int p = lo;
        for (; p + 1 < hi; p += 2) {
            int s0 = g_csr_src[p], s1 = g_csr_src[p + 1];
            float2 v0 = *(const float2*)(g_z2 + (size_t)s0 * OUT_F + c);
            float2 v1 = *(const float2*)(g_z2 + (size_t)s1 * OUT_F + c);
            a0.x += v0.x; a0.y += v0.y;
            a1.x += v1.x; a1.y += v1.y;
        }
        if (p < hi) {
            int s = g_csr_src[p];
            float2 v = *(const float2*)(g_z2 + (size_t)s * OUT_F + c);
            a0.x += v.x; a0.y += v.y;
        }
        float invd = 1.0f / fmaxf((float)(hi - lo), 1.0f);
        acc[j][0] += (a0.x + a1.x) * invd;
        acc[j][1] += (a0.y + a1.y) * invd;
    }

    float2 b = *(const float2*)(b2 + c);
    #pragma unroll
    for (int j = 0; j < 8; j++) {
        float2 r;
        r.x = acc[j][0] + b.x;
        r.y = acc[j][1] + b.y;
        *(float2*)(out + (size_t)(n0 + j) * OUT_F + c) = r;
    }
}

extern "C" void kernel_launch(void* const* d_in, const int* in_sizes, int n_in,
                              void* d_out, int out_size) {
    const float* nfeat = (const float*)d_in[0];
    const float* efeat = (const float*)d_in[1];
    const int*   src   = (const int*)  d_in[2];
    const int*   dst   = (const int*)  d_in[3];
    const float* We    = (const float*)d_in[4];
    const float* be    = (const float*)d_in[5];
    const float* W1s   = (const float*)d_in[6];
    const float* W1n   = (const float*)d_in[7];
    const float* b1    = (const float*)d_in[8];
    const float* W2s   = (const float*)d_in[9];
    const float* W2n   = (const float*)d_in[10];
    const float* b2    = (const float*)d_in[11];
    float* out = (float*)d_out;

    const int TPB = 256;
    const int edge_blocks = (N_EDGES + TPB - 1) / TPB;
    const int node_blocks = (N_NODES + TPB - 1) / TPB;
    const int g0_blocks   = (N_NODES + 15) / 16;
    const int gw_blocks   = (N_NODES + 7) / 8;
    const int sage_blocks = (((N_NODES + 7) / 8) * 32 + TPB - 1) / TPB;

    k_zero_hist<<<node_blocks, TPB>>>();
    k_hist     <<<edge_blocks, TPB>>>(dst);
    k_scan     <<<1, SCAN_T>>>();
    k_place    <<<edge_blocks, TPB>>>(src, dst);
    k_edge_mlp <<<edge_blocks, TPB>>>(efeat, nfeat, We, be);
    k_gather0  <<<g0_blocks, TPB>>>(nfeat);
    k_gather_h <<<gw_blocks, TPB>>>();
    k_sage1    <<<sage_blocks, TPB>>>(W1s, W1n, b1);
    k_premul2  <<<sage_blocks, TPB>>>(W2n);
    k_sage2f   <<<sage_blocks, TPB>>>(W2s, b2, out);
}